// round 3
// baseline (speedup 1.0000x reference)
#include <cuda_runtime.h>
#include <cuda_bf16.h>
#include <cstdint>

#define NB   32
#define CIN  256
#define COUT 256
#define HH   56
#define WW   56
#define PW   58
#define IMG  (PW*PW)        // 3364 padded elems per channel
#define TM   128
#define TN   64
#define TK   32

// Static device scratch (allocation-free rule)
__device__ __align__(256) float         g_xpad[(size_t)NB*CIN*IMG + 64];
__device__ __align__(256) __nv_bfloat16 g_wb[COUT*2304];

// ---------------------------------------------------------------------------
// Prep 1: zero-padded input  g_xpad[b][ci][py*58+px]
// ---------------------------------------------------------------------------
__global__ void pad_kernel(const float* __restrict__ x) {
    long long total = (long long)NB*CIN*IMG + 64;
    long long i = (long long)blockIdx.x*blockDim.x + threadIdx.x;
    if (i >= total) return;
    float v = 0.f;
    if (i < (long long)NB*CIN*IMG) {
        int img = (int)(i / IMG);
        int r   = (int)(i % IMG);
        int py = r / PW, px = r % PW;
        if (py >= 1 && py <= HH && px >= 1 && px <= WW)
            v = x[((long long)img*HH + (py-1))*WW + (px-1)];
    }
    g_xpad[i] = v;
}

// ---------------------------------------------------------------------------
// Prep 2: weights -> bf16, k-order = tap*256 + ci   (values exactly -1/0/+1)
// ---------------------------------------------------------------------------
__global__ void wprep_kernel(const float* __restrict__ qw) {
    int i = blockIdx.x*blockDim.x + threadIdx.x;
    if (i < COUT*2304) {
        int co = i / 2304, rest = i % 2304;
        int ci = rest / 9, tap = rest % 9;
        g_wb[co*2304 + tap*256 + ci] = __float2bfloat16(qw[i]);
    }
}

// ---------------------------------------------------------------------------
// PTX helpers
// ---------------------------------------------------------------------------
__device__ __forceinline__ uint32_t smem_u32(const void* p) {
    uint32_t a;
    asm("{ .reg .u64 t; cvta.to.shared.u64 t, %1; cvt.u32.u64 %0, t; }"
        : "=r"(a) : "l"(p));
    return a;
}
__device__ __forceinline__ void cp_async16(uint32_t dst, const void* src) {
    asm volatile("cp.async.cg.shared.global [%0], [%1], 16;\n" :: "r"(dst), "l"(src));
}
__device__ __forceinline__ void cp_commit() {
    asm volatile("cp.async.commit_group;\n" ::: "memory");
}
__device__ __forceinline__ void cp_wait0() {
    asm volatile("cp.async.wait_group 0;\n" ::: "memory");
}
__device__ __forceinline__ void ldsm4(uint32_t* r, uint32_t a) {
    asm volatile("ldmatrix.sync.aligned.m8n8.x4.shared.b16 {%0,%1,%2,%3}, [%4];"
        : "=r"(r[0]), "=r"(r[1]), "=r"(r[2]), "=r"(r[3]) : "r"(a));
}
__device__ __forceinline__ void ldsm2t(uint32_t* r, uint32_t a) {
    asm volatile("ldmatrix.sync.aligned.m8n8.x2.trans.shared.b16 {%0,%1}, [%2];"
        : "=r"(r[0]), "=r"(r[1]) : "r"(a));
}
__device__ __forceinline__ void mma16816(float* c, const uint32_t* a, const uint32_t* b) {
    asm("mma.sync.aligned.m16n8k16.row.col.f32.bf16.bf16.f32 "
        "{%0,%1,%2,%3}, {%4,%5,%6,%7}, {%8,%9}, {%0,%1,%2,%3};"
        : "+f"(c[0]), "+f"(c[1]), "+f"(c[2]), "+f"(c[3])
        : "r"(a[0]), "r"(a[1]), "r"(a[2]), "r"(a[3]), "r"(b[0]), "r"(b[1]));
}

// ---------------------------------------------------------------------------
// Implicit-GEMM conv:  D[co,p'] = sum_k W[co,k] * (Xhi[k,p'] + Xlo[k,p'])
// grid = (51 p'-tiles, 2 co-tiles, 32 batches), 256 threads
// ---------------------------------------------------------------------------
__global__ __launch_bounds__(256, 2)
void conv_kernel(const float* __restrict__ scale,
                 const float* __restrict__ bias,
                 float* __restrict__ out)
{
    __shared__ __align__(16) __nv_bfloat16 sA [2][TM*TK];   // 16 KB
    __shared__ __align__(16) __nv_bfloat16 sBh[2][TK*TN];   //  8 KB
    __shared__ __align__(16) __nv_bfloat16 sBl[2][TK*TN];   //  8 KB

    const int tid  = threadIdx.x;
    const int lane = tid & 31;
    const int warp = tid >> 5;
    const int wm   = warp & 3;          // 4 m-warps (co)
    const int wn   = warp >> 2;         // 2 n-warps (p')
    const int b       = blockIdx.z;
    const int co_base = blockIdx.y * TM;
    const int p0      = blockIdx.x * TN;

    const int col = tid & 63;           // p' column within tile (B load map)
    const int ro  = tid >> 6;           // row offset 0..3

    const uint32_t sA_u  = smem_u32(&sA[0][0]);
    const uint32_t sBh_u = smem_u32(&sBh[0][0]);
    const uint32_t sBl_u = smem_u32(&sBl[0][0]);

    float acc[2][4][4];
    #pragma unroll
    for (int mt = 0; mt < 2; ++mt)
        #pragma unroll
        for (int nt = 0; nt < 4; ++nt)
            #pragma unroll
            for (int r = 0; r < 4; ++r) acc[mt][nt][r] = 0.f;

    // A tile: cp.async, row co pitch 64B (4x16B), swizzled slot = kg ^ ((co>>1)&3)
    auto loadA = [&](int tap, int cc, int bufi) {
        int co = tid >> 1;
        const __nv_bfloat16* src = g_wb + (size_t)(co_base + co)*2304 + tap*256 + cc*TK;
        uint32_t dbase = sA_u + (uint32_t)bufi*(TM*TK*2) + (uint32_t)co*64;
        #pragma unroll
        for (int q = 0; q < 2; ++q) {
            int kg = (tid & 1)*2 + q;   // 16B chunk 0..3
            uint32_t d = dbase + (uint32_t)((kg ^ ((co>>1)&3)) << 4);
            cp_async16(d, (const void*)(src + kg*8));
        }
    };
    // B tile: fp32 gmem loads, 8 rows per thread (rows j*4+ro, fixed col)
    auto loadB = [&](int tap, int cc, float* xv) {
        int tap_off = (tap/3)*PW + (tap%3);
        const float* p = g_xpad + (size_t)(b*CIN + cc*TK + ro)*IMG + tap_off + p0 + col;
        #pragma unroll
        for (int j = 0; j < 8; ++j) xv[j] = p[(size_t)j*4*IMG];
    };
    // fp32 -> (hi,lo) bf16, swizzled stores; row pitch 128B, slot = (col>>3)^(row&7)
    auto convB = [&](const float* xv, int bufi) {
        #pragma unroll
        for (int j = 0; j < 8; ++j) {
            int row = j*4 + ro;
            float xf = xv[j];
            __nv_bfloat16 hb = __float2bfloat16(xf);
            float hf = __bfloat162float(hb);
            __nv_bfloat16 lb = __float2bfloat16(xf - hf);
            int off = row*TN + ((((col>>3) ^ (row&7)) << 3) | (col & 7));
            sBh[bufi][off] = hb;
            sBl[bufi][off] = lb;
        }
    };
    auto compute = [&](int bufi) {
        uint32_t ab = sA_u  + (uint32_t)bufi*(TM*TK*2);
        uint32_t hb = sBh_u + (uint32_t)bufi*(TK*TN*2);
        uint32_t lb = sBl_u + (uint32_t)bufi*(TK*TN*2);
        #pragma unroll
        for (int s = 0; s < 2; ++s) {
            uint32_t a[2][4];
            #pragma unroll
            for (int mt = 0; mt < 2; ++mt) {
                int m  = wm*32 + mt*16 + (lane & 15);
                int kg = s*2 + (lane >> 4);
                uint32_t ad = ab + (uint32_t)m*64 + (uint32_t)((kg ^ ((m>>1)&3)) << 4);
                ldsm4(a[mt], ad);
            }
            int kb = s*16 + (lane & 15);
            #pragma unroll
            for (int nt = 0; nt < 4; ++nt) {
                int n0 = wn*32 + nt*8;
                uint32_t slot = (uint32_t)(((n0>>3) ^ (kb&7)) << 4);
                uint32_t bh[2], bl2[2];
                ldsm2t(bh,  hb + (uint32_t)kb*128 + slot);
                ldsm2t(bl2, lb + (uint32_t)kb*128 + slot);
                #pragma unroll
                for (int mt = 0; mt < 2; ++mt) {
                    mma16816(acc[mt][nt], a[mt], bh);
                    mma16816(acc[mt][nt], a[mt], bl2);
                }
            }
        }
    };

    // ---- pipeline: 9 taps x 8 ci-chunks = 72 K-iterations -------------------
    {
        float xv[8];
        loadA(0, 0, 0); cp_commit();
        loadB(0, 0, xv);
        convB(xv, 0);
        cp_wait0();
        __syncthreads();
    }
    for (int it = 0; it < 72; ++it) {
        int cur = it & 1, nxt = cur ^ 1;
        float xv[8];
        if (it < 71) {
            int t2 = it + 1;
            loadA(t2 >> 3, t2 & 7, nxt); cp_commit();
            loadB(t2 >> 3, t2 & 7, xv);          // gmem latency hidden by compute
        }
        compute(cur);
        if (it < 71) {
            convB(xv, nxt);
            cp_wait0();
        }
        __syncthreads();
    }

    // ---- epilogue: scale*acc + bias, discard x>=56 / y>=56 ------------------
    #pragma unroll
    for (int mt = 0; mt < 2; ++mt) {
        #pragma unroll
        for (int half = 0; half < 2; ++half) {
            int co = co_base + wm*32 + mt*16 + (lane>>2) + half*8;
            float sc = __ldg(&scale[co]);
            float bs = __ldg(&bias[co]);
            #pragma unroll
            for (int nt = 0; nt < 4; ++nt) {
                int n = p0 + wn*32 + nt*8 + (lane&3)*2;
                int y = n / PW, x2 = n % PW;
                if (x2 < WW && y < HH) {
                    float2 v;
                    v.x = sc*acc[mt][nt][half*2+0] + bs;
                    v.y = sc*acc[mt][nt][half*2+1] + bs;
                    *(float2*)&out[(((size_t)b*COUT + co)*HH + y)*WW + x2] = v;
                }
            }
        }
    }
}

// ---------------------------------------------------------------------------
extern "C" void kernel_launch(void* const* d_in, const int* in_sizes, int n_in,
                              void* d_out, int out_size) {
    const float* x     = (const float*)d_in[0];
    const float* scale = (const float*)d_in[1];
    const float* qw    = (const float*)d_in[2];
    const float* bias  = (const float*)d_in[3];
    float* out = (float*)d_out;

    long long padN = (long long)NB*CIN*IMG + 64;
    pad_kernel<<<(unsigned)((padN + 255)/256), 256>>>(x);
    wprep_kernel<<<(COUT*2304 + 255)/256, 256>>>(qw);

    dim3 grid(51, 2, NB);   // 51 p'-tiles of 64 (58*56=3248), 2 co-tiles, 32 batches
    conv_kernel<<<grid, 256>>>(scale, bias, out);
}

// round 4
// speedup vs baseline: 1.6758x; 1.6758x over previous
#include <cuda_runtime.h>
#include <cuda_fp16.h>
#include <cstdint>

#define NB   32
#define CIN  256
#define COUT 256
#define HH   56
#define WW   56
#define PW   58
#define IMG  (PW*PW)        // 3364 padded elems per channel
#define TM   128
#define TN   128
#define TK   32
#define GUARD 128

// Static device scratch (allocation-free rule)
__device__ __align__(256) __half g_xh[(size_t)NB*CIN*IMG + GUARD];  // padded fp16 input
__device__ __align__(256) __half g_wh[COUT*2304];                   // fp16 weights, k=(tap*256+ci)

// ---------------------------------------------------------------------------
// Prep 1: zero-padded fp16 input  g_xh[b][ci][py*58+px]
// ---------------------------------------------------------------------------
__global__ void pad_kernel(const float* __restrict__ x) {
    long long total = (long long)NB*CIN*IMG + GUARD;
    long long i = (long long)blockIdx.x*blockDim.x + threadIdx.x;
    if (i >= total) return;
    float v = 0.f;
    if (i < (long long)NB*CIN*IMG) {
        int img = (int)(i / IMG);
        int r   = (int)(i % IMG);
        int py = r / PW, px = r % PW;
        if (py >= 1 && py <= HH && px >= 1 && px <= WW)
            v = x[((long long)img*HH + (py-1))*WW + (px-1)];
    }
    g_xh[i] = __float2half(v);
}

// ---------------------------------------------------------------------------
// Prep 2: weights -> fp16, k-order = tap*256 + ci   (values exactly -1/0/+1)
// ---------------------------------------------------------------------------
__global__ void wprep_kernel(const float* __restrict__ qw) {
    int i = blockIdx.x*blockDim.x + threadIdx.x;
    if (i < COUT*2304) {
        int co = i / 2304, rest = i % 2304;
        int ci = rest / 9, tap = rest % 9;
        g_wh[co*2304 + tap*256 + ci] = __float2half(qw[i]);
    }
}

// ---------------------------------------------------------------------------
// PTX helpers
// ---------------------------------------------------------------------------
__device__ __forceinline__ uint32_t smem_u32(const void* p) {
    uint32_t a;
    asm("{ .reg .u64 t; cvta.to.shared.u64 t, %1; cvt.u32.u64 %0, t; }"
        : "=r"(a) : "l"(p));
    return a;
}
__device__ __forceinline__ void cp_async16(uint32_t dst, const void* src) {
    asm volatile("cp.async.cg.shared.global [%0], [%1], 16;\n" :: "r"(dst), "l"(src));
}
__device__ __forceinline__ void cp_commit() {
    asm volatile("cp.async.commit_group;\n" ::: "memory");
}
__device__ __forceinline__ void cp_wait0() {
    asm volatile("cp.async.wait_group 0;\n" ::: "memory");
}
__device__ __forceinline__ void ldsm4(uint32_t* r, uint32_t a) {
    asm volatile("ldmatrix.sync.aligned.m8n8.x4.shared.b16 {%0,%1,%2,%3}, [%4];"
        : "=r"(r[0]), "=r"(r[1]), "=r"(r[2]), "=r"(r[3]) : "r"(a));
}
__device__ __forceinline__ void ldsm2t(uint32_t* r, uint32_t a) {
    asm volatile("ldmatrix.sync.aligned.m8n8.x2.trans.shared.b16 {%0,%1}, [%2];"
        : "=r"(r[0]), "=r"(r[1]) : "r"(a));
}
__device__ __forceinline__ void mma16816(float* c, const uint32_t* a, const uint32_t* b) {
    asm("mma.sync.aligned.m16n8k16.row.col.f32.f16.f16.f32 "
        "{%0,%1,%2,%3}, {%4,%5,%6,%7}, {%8,%9}, {%0,%1,%2,%3};"
        : "+f"(c[0]), "+f"(c[1]), "+f"(c[2]), "+f"(c[3])
        : "r"(a[0]), "r"(a[1]), "r"(a[2]), "r"(a[3]), "r"(b[0]), "r"(b[1]));
}

// ---------------------------------------------------------------------------
// Implicit-GEMM conv:  D[co,p'] = sum_k W[co,k] * X[k,p']   (fp16 x fp16 -> fp32)
// grid = (26 p'-tiles of 128, 2 co-tiles, 32 batches), 256 threads
// ---------------------------------------------------------------------------
__global__ __launch_bounds__(256, 2)
void conv_kernel(const float* __restrict__ scale,
                 const float* __restrict__ bias,
                 float* __restrict__ out)
{
    __shared__ __align__(16) __half sA[2][TM*TK];   // 16 KB
    __shared__ __align__(16) __half sB[2][TK*TN];   // 16 KB

    const int tid  = threadIdx.x;
    const int lane = tid & 31;
    const int warp = tid >> 5;
    const int wm   = warp & 3;          // 4 m-warps (co)
    const int wn   = warp >> 2;         // 2 n-warps (p'), 64 cols each
    const int b       = blockIdx.z;
    const int co_base = blockIdx.y * TM;
    const int p0      = blockIdx.x * TN;

    const int col = tid & 127;          // p' column within tile (B load map)
    const int ro  = tid >> 7;           // row offset 0..1

    const uint32_t sA_u = smem_u32(&sA[0][0]);
    const uint32_t sB_u = smem_u32(&sB[0][0]);

    float acc[2][8][4];
    #pragma unroll
    for (int mt = 0; mt < 2; ++mt)
        #pragma unroll
        for (int nt = 0; nt < 8; ++nt)
            #pragma unroll
            for (int r = 0; r < 4; ++r) acc[mt][nt][r] = 0.f;

    // A tile: cp.async, row co pitch 64B (4x16B), swizzle slot = kg ^ ((co>>1)&3)
    auto loadA = [&](int tap, int cc, int bufi) {
        int co = tid >> 1;
        const __half* src = g_wh + (size_t)(co_base + co)*2304 + tap*256 + cc*TK;
        uint32_t dbase = sA_u + (uint32_t)bufi*(TM*TK*2) + (uint32_t)co*64;
        #pragma unroll
        for (int q = 0; q < 2; ++q) {
            int kg = (tid & 1)*2 + q;   // 16B chunk 0..3
            uint32_t d = dbase + (uint32_t)((kg ^ ((co>>1)&3)) << 4);
            cp_async16(d, (const void*)(src + kg*8));
        }
    };
    // B tile: fp16 gmem loads, 16 rows per thread (rows j*2+ro, fixed col)
    auto loadB = [&](int tap, int cc, __half* xv) {
        int tap_off = (tap/3)*PW + (tap%3);
        const __half* p = g_xh + (size_t)(b*CIN + cc*TK + ro)*IMG + tap_off + p0 + col;
        #pragma unroll
        for (int j = 0; j < 16; ++j) xv[j] = p[(size_t)j*2*IMG];
    };
    // swizzled stores: row pitch 256B (16 chunks), chunk = (col>>3) ^ (row&7)
    auto convB = [&](const __half* xv, int bufi) {
        #pragma unroll
        for (int j = 0; j < 16; ++j) {
            int row = j*2 + ro;
            int off = row*TN + ((((col>>3) ^ (row&7)) << 3) | (col & 7));
            sB[bufi][off] = xv[j];
        }
    };
    auto compute = [&](int bufi) {
        uint32_t ab = sA_u + (uint32_t)bufi*(TM*TK*2);
        uint32_t bb = sB_u + (uint32_t)bufi*(TK*TN*2);
        #pragma unroll
        for (int s = 0; s < 2; ++s) {
            uint32_t a[2][4];
            #pragma unroll
            for (int mt = 0; mt < 2; ++mt) {
                int m  = wm*32 + mt*16 + (lane & 15);
                int kg = s*2 + (lane >> 4);
                uint32_t ad = ab + (uint32_t)m*64 + (uint32_t)((kg ^ ((m>>1)&3)) << 4);
                ldsm4(a[mt], ad);
            }
            int kb = s*16 + (lane & 15);
            #pragma unroll
            for (int nt = 0; nt < 8; ++nt) {
                int n0 = wn*64 + nt*8;
                uint32_t slot = (uint32_t)((((n0>>3) & 15) ^ (kb&7)) << 4);
                uint32_t bf[2];
                ldsm2t(bf, bb + (uint32_t)kb*256 + slot);
                mma16816(acc[0][nt], a[0], bf);
                mma16816(acc[1][nt], a[1], bf);
            }
        }
    };

    // ---- pipeline: 9 taps x 8 ci-chunks = 72 K-iterations -------------------
    {
        __half xv[16];
        loadA(0, 0, 0); cp_commit();
        loadB(0, 0, xv);
        convB(xv, 0);
        cp_wait0();
        __syncthreads();
    }
    for (int it = 0; it < 72; ++it) {
        int cur = it & 1, nxt = cur ^ 1;
        __half xv[16];
        if (it < 71) {
            int t2 = it + 1;
            loadA(t2 >> 3, t2 & 7, nxt); cp_commit();
            loadB(t2 >> 3, t2 & 7, xv);          // gmem latency hidden by compute
        }
        compute(cur);
        if (it < 71) {
            convB(xv, nxt);
            cp_wait0();
        }
        __syncthreads();
    }

    // ---- epilogue: scale*acc + bias, discard x>=56 / y>=56 ------------------
    #pragma unroll
    for (int mt = 0; mt < 2; ++mt) {
        #pragma unroll
        for (int half = 0; half < 2; ++half) {
            int co = co_base + wm*32 + mt*16 + (lane>>2) + half*8;
            float sc = __ldg(&scale[co]);
            float bs = __ldg(&bias[co]);
            #pragma unroll
            for (int nt = 0; nt < 8; ++nt) {
                int n = p0 + wn*64 + nt*8 + (lane&3)*2;
                int y = n / PW, x2 = n % PW;
                if (x2 < WW && y < HH) {
                    float2 v;
                    v.x = sc*acc[mt][nt][half*2+0] + bs;
                    v.y = sc*acc[mt][nt][half*2+1] + bs;
                    *(float2*)&out[(((size_t)b*COUT + co)*HH + y)*WW + x2] = v;
                }
            }
        }
    }
}

// ---------------------------------------------------------------------------
extern "C" void kernel_launch(void* const* d_in, const int* in_sizes, int n_in,
                              void* d_out, int out_size) {
    const float* x     = (const float*)d_in[0];
    const float* scale = (const float*)d_in[1];
    const float* qw    = (const float*)d_in[2];
    const float* bias  = (const float*)d_in[3];
    float* out = (float*)d_out;

    long long padN = (long long)NB*CIN*IMG + GUARD;
    pad_kernel<<<(unsigned)((padN + 255)/256), 256>>>(x);
    wprep_kernel<<<(COUT*2304 + 255)/256, 256>>>(qw);

    dim3 grid(26, 2, NB);   // 26 p'-tiles of 128 (58*56=3248), 2 co-tiles, 32 batches
    conv_kernel<<<grid, 256>>>(scale, bias, out);
}

// round 6
// speedup vs baseline: 1.9865x; 1.1854x over previous
#include <cuda_runtime.h>
#include <cuda_fp16.h>
#include <cstdint>

#define NB   32
#define CIN  256
#define COUT 256
#define HH   56
#define WW   56
#define PW   58
#define IMG  (PW*PW)          // 3364
#define IMGP 3368             // padded image stride (p dimension)
#define GTAIL (81*256)        // tail guard halves (tap overreach on last image)
#define TM   128
#define TN   128
#define TK   32
#define ASZ  (TM*TK*2)        // 8192 B
#define BSZ  (TK*TN*2)        // 8192 B
#define NSTG 3

// channels-last padded input: g_xcl[b][p][ci], fp16
__device__ __align__(256) __half g_xcl[(size_t)NB*IMGP*CIN + GTAIL];
__device__ __align__(256) __half g_wh[COUT*2304];   // weights, k = tap*256 + ci

// ---------------------------------------------------------------------------
// Prep 0: zero-fill g_xcl (vectorized)
// ---------------------------------------------------------------------------
__global__ void zero_kernel() {
    size_t total16 = ((size_t)NB*IMGP*CIN + GTAIL) / 8;   // uint4 count
    size_t i = (size_t)blockIdx.x*blockDim.x + threadIdx.x;
    if (i < total16) ((uint4*)g_xcl)[i] = make_uint4(0,0,0,0);
}

// ---------------------------------------------------------------------------
// Prep 1: transpose-pad  x[b][ci][h][w] (fp32) -> g_xcl[b][(y+1)*58+(x+1)][ci] (fp16)
// grid = (49 p-chunks of 64, 8 ci-chunks of 32, 32 b), 256 threads
// ---------------------------------------------------------------------------
__global__ void tpad_kernel(const float* __restrict__ x) {
    __shared__ __half st[32][68];   // [ci][p] +pad
    const int tid = threadIdx.x;
    const int pc  = blockIdx.x * 64;
    const int cic = blockIdx.y * 32;
    const int b   = blockIdx.z;

    // load: 32 ci rows x 64 p, float4 x2 per thread
    {
        int ci_r = tid >> 3;          // 0..31
        int pj   = tid & 7;           // 0..7
        const float* src = x + ((size_t)(b*CIN + cic + ci_r)*3136 + pc + pj*8);
        float4 v0 = *(const float4*)(src);
        float4 v1 = *(const float4*)(src + 4);
        st[ci_r][pj*8+0] = __float2half(v0.x);
        st[ci_r][pj*8+1] = __float2half(v0.y);
        st[ci_r][pj*8+2] = __float2half(v0.z);
        st[ci_r][pj*8+3] = __float2half(v0.w);
        st[ci_r][pj*8+4] = __float2half(v1.x);
        st[ci_r][pj*8+5] = __float2half(v1.y);
        st[ci_r][pj*8+6] = __float2half(v1.z);
        st[ci_r][pj*8+7] = __float2half(v1.w);
    }
    __syncthreads();

    // store: 64 p x 32 ci, 16B per thread
    {
        int pw = tid >> 2;            // 0..63
        int g  = tid & 3;             // 0..3 (8 ci each)
        int p  = pc + pw;
        int y  = p / 56, xx = p % 56;
        int ppad = (y+1)*PW + (xx+1);
        __half h[8];
        #pragma unroll
        for (int j = 0; j < 8; ++j) h[j] = st[g*8+j][pw];
        __half* dst = g_xcl + ((size_t)b*IMGP + ppad)*CIN + cic + g*8;
        *(uint4*)dst = *(uint4*)h;
    }
}

// ---------------------------------------------------------------------------
// Prep 2: weights -> fp16, k = tap*256 + ci
// ---------------------------------------------------------------------------
__global__ void wprep_kernel(const float* __restrict__ qw) {
    int i = blockIdx.x*blockDim.x + threadIdx.x;
    if (i < COUT*2304) {
        int co = i / 2304, rest = i % 2304;
        int ci = rest / 9, tap = rest % 9;
        g_wh[co*2304 + tap*256 + ci] = __float2half(qw[i]);
    }
}

// ---------------------------------------------------------------------------
// PTX helpers
// ---------------------------------------------------------------------------
__device__ __forceinline__ uint32_t smem_u32(const void* p) {
    uint32_t a;
    asm("{ .reg .u64 t; cvta.to.shared.u64 t, %1; cvt.u32.u64 %0, t; }"
        : "=r"(a) : "l"(p));
    return a;
}
__device__ __forceinline__ void cp_async16(uint32_t dst, const void* src) {
    asm volatile("cp.async.cg.shared.global [%0], [%1], 16;\n" :: "r"(dst), "l"(src));
}
__device__ __forceinline__ void cp_commit() {
    asm volatile("cp.async.commit_group;\n" ::: "memory");
}
__device__ __forceinline__ void cp_wait0() {
    asm volatile("cp.async.wait_group 0;\n" ::: "memory");
}
__device__ __forceinline__ void cp_wait1() {
    asm volatile("cp.async.wait_group 1;\n" ::: "memory");
}
__device__ __forceinline__ void ldsm4(uint32_t* r, uint32_t a) {
    asm volatile("ldmatrix.sync.aligned.m8n8.x4.shared.b16 {%0,%1,%2,%3}, [%4];"
        : "=r"(r[0]), "=r"(r[1]), "=r"(r[2]), "=r"(r[3]) : "r"(a));
}
__device__ __forceinline__ void mma16816(float* c, const uint32_t* a, const uint32_t* b) {
    asm("mma.sync.aligned.m16n8k16.row.col.f32.f16.f16.f32 "
        "{%0,%1,%2,%3}, {%4,%5,%6,%7}, {%8,%9}, {%0,%1,%2,%3};"
        : "+f"(c[0]), "+f"(c[1]), "+f"(c[2]), "+f"(c[3])
        : "r"(a[0]), "r"(a[1]), "r"(a[2]), "r"(a[3]), "r"(b[0]), "r"(b[1]));
}

// ---------------------------------------------------------------------------
// Implicit-GEMM conv:  D[co,p'] = sum_k W[co,k] * X[k,p']
// B smem is n-major [n][k(ci32)]: 64B rows, fully cp.async-fed.
// grid = (26 p'-tiles of 128, 2 co-tiles, 32 batches), 256 threads, 3 stages
// ---------------------------------------------------------------------------
__global__ __launch_bounds__(256, 2)
void conv_kernel(const float* __restrict__ scale,
                 const float* __restrict__ bias,
                 float* __restrict__ out)
{
    __shared__ __align__(16) __half sA[NSTG][TM*TK];   // 3 x 8 KB
    __shared__ __align__(16) __half sB[NSTG][TN*TK];   // 3 x 8 KB  (n-major)

    const int tid  = threadIdx.x;
    const int lane = tid & 31;
    const int warp = tid >> 5;
    const int wm   = warp & 3;          // 4 m-warps (co, 32 each)
    const int wn   = warp >> 2;         // 2 n-warps (p', 64 each)
    const int b       = blockIdx.z;
    const int co_base = blockIdx.y * TM;
    const int p0      = blockIdx.x * TN;

    const uint32_t sA_u = smem_u32(&sA[0][0]);
    const uint32_t sB_u = smem_u32(&sB[0][0]);

    float acc[2][8][4];
    #pragma unroll
    for (int mt = 0; mt < 2; ++mt)
        #pragma unroll
        for (int nt = 0; nt < 8; ++nt)
            #pragma unroll
            for (int r = 0; r < 4; ++r) acc[mt][nt][r] = 0.f;

    // A tile: row co pitch 64B (4x16B chunks), slot = kg ^ ((co>>1)&3)
    auto loadA = [&](int it2, int bufi) {
        int tap = it2 >> 3, cc = it2 & 7;
        int co = tid >> 1;
        const __half* src = g_wh + (size_t)(co_base + co)*2304 + tap*256 + cc*TK;
        uint32_t dbase = sA_u + (uint32_t)bufi*ASZ + (uint32_t)co*64;
        #pragma unroll
        for (int q = 0; q < 2; ++q) {
            int kg = (tid & 1)*2 + q;
            cp_async16(dbase + (uint32_t)((kg ^ ((co>>1)&3)) << 4), src + kg*8);
        }
    };
    // B tile: row n pitch 64B (4x16B chunks of ci), slot = c ^ ((n>>1)&3)
    auto loadB = [&](int it2, int bufi) {
        int tap = it2 >> 3, cc = it2 & 7;
        int tap_off = (tap/3)*PW + (tap%3);
        int n  = tid & 127;
        int c0 = (tid >> 7) * 2;
        const __half* src = g_xcl + ((size_t)b*IMGP + p0 + n + tap_off)*CIN + cc*TK;
        uint32_t dbase = sB_u + (uint32_t)bufi*BSZ + (uint32_t)n*64;
        #pragma unroll
        for (int q = 0; q < 2; ++q) {
            int c = c0 + q;
            cp_async16(dbase + (uint32_t)((c ^ ((n>>1)&3)) << 4), src + c*8);
        }
    };
    auto compute = [&](int bufi) {
        uint32_t ab = sA_u + (uint32_t)bufi*ASZ;
        uint32_t bb = sB_u + (uint32_t)bufi*BSZ;
        #pragma unroll
        for (int s = 0; s < 2; ++s) {
            uint32_t a[2][4];
            #pragma unroll
            for (int mt = 0; mt < 2; ++mt) {
                int m  = wm*32 + mt*16 + (lane & 15);
                int kg = s*2 + (lane >> 4);
                ldsm4(a[mt], ab + (uint32_t)m*64 + (uint32_t)((kg ^ ((m>>1)&3)) << 4));
            }
            #pragma unroll
            for (int pr = 0; pr < 4; ++pr) {       // pair of n-tiles per ldsm4
                int grp = lane >> 3, r = lane & 7;
                int n = wn*64 + pr*16 + ((grp & 2) << 2) + r;
                int c = s*2 + (grp & 1);
                uint32_t bfr[4];                   // (n0,k0)(n0,k8)(n0+8,k0)(n0+8,k8)
                ldsm4(bfr, bb + (uint32_t)n*64 + (uint32_t)((c ^ ((n>>1)&3)) << 4));
                mma16816(acc[0][2*pr+0], a[0], &bfr[0]);
                mma16816(acc[1][2*pr+0], a[1], &bfr[0]);
                mma16816(acc[0][2*pr+1], a[0], &bfr[2]);
                mma16816(acc[1][2*pr+1], a[1], &bfr[2]);
            }
        }
    };

    // ---- 3-stage pipeline over 72 K-iterations (9 taps x 8 ci-chunks) -------
    loadA(0, 0); loadB(0, 0); cp_commit();
    loadA(1, 1); loadB(1, 1); cp_commit();

    for (int it = 0; it < 72; ++it) {
        if (it >= 70) cp_wait0(); else cp_wait1();
        __syncthreads();
        int it2 = it + 2;
        if (it2 < 72) {
            int nb = it2 % NSTG;
            loadA(it2, nb); loadB(it2, nb);
        }
        cp_commit();
        compute(it % NSTG);
    }

    // ---- epilogue: scale*acc + bias, discard x>=56 / y>=56 ------------------
    #pragma unroll
    for (int mt = 0; mt < 2; ++mt) {
        #pragma unroll
        for (int half = 0; half < 2; ++half) {
            int co = co_base + wm*32 + mt*16 + (lane>>2) + half*8;
            float sc = __ldg(&scale[co]);
            float bs = __ldg(&bias[co]);
            #pragma unroll
            for (int nt = 0; nt < 8; ++nt) {
                int n = p0 + wn*64 + nt*8 + (lane&3)*2;
                int y = n / PW, x2 = n % PW;
                if (x2 < WW && y < HH) {
                    float2 v;
                    v.x = sc*acc[mt][nt][half*2+0] + bs;
                    v.y = sc*acc[mt][nt][half*2+1] + bs;
                    *(float2*)&out[(((size_t)b*COUT + co)*HH + y)*WW + x2] = v;
                }
            }
        }
    }
}

// ---------------------------------------------------------------------------
extern "C" void kernel_launch(void* const* d_in, const int* in_sizes, int n_in,
                              void* d_out, int out_size) {
    const float* x     = (const float*)d_in[0];
    const float* scale = (const float*)d_in[1];
    const float* qw    = (const float*)d_in[2];
    const float* bias  = (const float*)d_in[3];
    float* out = (float*)d_out;

    size_t z16 = ((size_t)NB*IMGP*CIN + GTAIL) / 8;
    zero_kernel<<<(unsigned)((z16 + 255)/256), 256>>>();
    dim3 tg(49, 8, NB);
    tpad_kernel<<<tg, 256>>>(x);
    wprep_kernel<<<(COUT*2304 + 255)/256, 256>>>(qw);

    dim3 grid(26, 2, NB);
    conv_kernel<<<grid, 256>>>(scale, bias, out);
}

// round 9
// speedup vs baseline: 2.1815x; 1.0982x over previous
#include <cuda_runtime.h>
#include <cuda_fp16.h>
#include <cstdint>

#define NB   32
#define CIN  256
#define COUT 256
#define HH   56
#define WW   56
#define PW   58
#define IMGP 3368             // padded image stride (p dimension)
#define GTAIL (81*256)        // tail guard halves (tap overreach on last image)

#define TM   128
#define TN   128
#define TK   64
#define NSTG 3
#define STG_BYTES 32768       // A 16KB + B 16KB
#define B_OFF 16384
#define SMEM_TOTAL (NSTG*STG_BYTES)   // 96 KB

// channels-last padded input: g_xcl[b][p][ci], fp16
__device__ __align__(256) __half g_xcl[(size_t)NB*IMGP*CIN + GTAIL];
__device__ __align__(256) __half g_wh[COUT*2304];   // weights, k = tap*256 + ci

// ---------------------------------------------------------------------------
// Prep 0: zero-fill g_xcl
// ---------------------------------------------------------------------------
__global__ void zero_kernel() {
    size_t total16 = ((size_t)NB*IMGP*CIN + GTAIL) / 8;
    size_t i = (size_t)blockIdx.x*blockDim.x + threadIdx.x;
    if (i < total16) ((uint4*)g_xcl)[i] = make_uint4(0,0,0,0);
}

// ---------------------------------------------------------------------------
// Prep 1: transpose-pad  x[b][ci][h][w] (fp32) -> g_xcl[b][(y+1)*58+(x+1)][ci]
// ---------------------------------------------------------------------------
__global__ void tpad_kernel(const float* __restrict__ x) {
    __shared__ __half st[32][68];
    const int tid = threadIdx.x;
    const int pc  = blockIdx.x * 64;
    const int cic = blockIdx.y * 32;
    const int b   = blockIdx.z;
    {
        int ci_r = tid >> 3;
        int pj   = tid & 7;
        const float* src = x + ((size_t)(b*CIN + cic + ci_r)*3136 + pc + pj*8);
        float4 v0 = *(const float4*)(src);
        float4 v1 = *(const float4*)(src + 4);
        st[ci_r][pj*8+0] = __float2half(v0.x);
        st[ci_r][pj*8+1] = __float2half(v0.y);
        st[ci_r][pj*8+2] = __float2half(v0.z);
        st[ci_r][pj*8+3] = __float2half(v0.w);
        st[ci_r][pj*8+4] = __float2half(v1.x);
        st[ci_r][pj*8+5] = __float2half(v1.y);
        st[ci_r][pj*8+6] = __float2half(v1.z);
        st[ci_r][pj*8+7] = __float2half(v1.w);
    }
    __syncthreads();
    {
        int pw = tid >> 2;
        int g  = tid & 3;
        int p  = pc + pw;
        int y  = p / 56, xx = p % 56;
        int ppad = (y+1)*PW + (xx+1);
        __half h[8];
        #pragma unroll
        for (int j = 0; j < 8; ++j) h[j] = st[g*8+j][pw];
        __half* dst = g_xcl + ((size_t)b*IMGP + ppad)*CIN + cic + g*8;
        *(uint4*)dst = *(uint4*)h;
    }
}

// ---------------------------------------------------------------------------
// Prep 2: weights -> fp16, k = tap*256 + ci
// ---------------------------------------------------------------------------
__global__ void wprep_kernel(const float* __restrict__ qw) {
    int i = blockIdx.x*blockDim.x + threadIdx.x;
    if (i < COUT*2304) {
        int co = i / 2304, rest = i % 2304;
        int ci = rest / 9, tap = rest % 9;
        g_wh[co*2304 + tap*256 + ci] = __float2half(qw[i]);
    }
}

// ---------------------------------------------------------------------------
// PTX helpers
// ---------------------------------------------------------------------------
__device__ __forceinline__ uint32_t smem_u32(const void* p) {
    uint32_t a;
    asm("{ .reg .u64 t; cvta.to.shared.u64 t, %1; cvt.u32.u64 %0, t; }"
        : "=r"(a) : "l"(p));
    return a;
}
__device__ __forceinline__ void cp_async16(uint32_t dst, const void* src) {
    asm volatile("cp.async.cg.shared.global [%0], [%1], 16;\n" :: "r"(dst), "l"(src));
}
__device__ __forceinline__ void cp_commit() {
    asm volatile("cp.async.commit_group;\n" ::: "memory");
}
template <int N>
__device__ __forceinline__ void cp_wait() {
    asm volatile("cp.async.wait_group %0;\n" :: "n"(N) : "memory");
}
__device__ __forceinline__ void ldsm4(uint32_t* r, uint32_t a) {
    asm volatile("ldmatrix.sync.aligned.m8n8.x4.shared.b16 {%0,%1,%2,%3}, [%4];"
        : "=r"(r[0]), "=r"(r[1]), "=r"(r[2]), "=r"(r[3]) : "r"(a));
}
__device__ __forceinline__ void mma16816(float* c, const uint32_t* a, const uint32_t* b) {
    asm("mma.sync.aligned.m16n8k16.row.col.f32.f16.f16.f32 "
        "{%0,%1,%2,%3}, {%4,%5,%6,%7}, {%8,%9}, {%0,%1,%2,%3};"
        : "+f"(c[0]), "+f"(c[1]), "+f"(c[2]), "+f"(c[3])
        : "r"(a[0]), "r"(a[1]), "r"(a[2]), "r"(a[3]), "r"(b[0]), "r"(b[1]));
}

// ---------------------------------------------------------------------------
// Implicit-GEMM conv:  D[co,p'] = sum_k W[co,k] * X[k,p']
// K = 2304 as 36 chunks of 64 (tap*4 + ci-quarter). 3-stage cp.async ring.
// Stage: A[128co x 64k] + B[128n x 64k], both 128B rows, SW128 swizzle.
// grid = (26 p'-tiles of 128, 2 co-tiles, 32 b), 256 threads, 2 CTAs/SM
// ---------------------------------------------------------------------------
__global__ __launch_bounds__(256, 2)
void conv_kernel(const float* __restrict__ scale,
                 const float* __restrict__ bias,
                 float* __restrict__ out)
{
    extern __shared__ __align__(16) char smem[];
    const uint32_t sb = smem_u32(smem);

    const int tid  = threadIdx.x;
    const int lane = tid & 31;
    const int warp = tid >> 5;
    const int wm   = warp & 3;          // 4 m-warps (co, 32 each)
    const int wn   = warp >> 2;         // 2 n-warps (p', 64 each)
    const int b       = blockIdx.z;
    const int co_base = blockIdx.y * TM;
    const int p0      = blockIdx.x * TN;

    float acc[2][8][4];
    #pragma unroll
    for (int mt = 0; mt < 2; ++mt)
        #pragma unroll
        for (int nt = 0; nt < 8; ++nt)
            #pragma unroll
            for (int r = 0; r < 4; ++r) acc[mt][nt][r] = 0.f;

    // Load one K-chunk (tap, 64 ci) into stage st. Row = co (A) / n (B),
    // 128B per row = 8 x 16B chunks, swizzled chunk' = c ^ (row&7).
    auto loadStage = [&](int kc, int st) {
        int tap = kc >> 2, ci0 = (kc & 3) * 64;
        int tap_off = (tap/3)*PW + (tap%3);
        int row   = tid >> 1;               // 0..127
        int cbase = (tid & 1) * 4;          // chunks 0-3 / 4-7
        const __half* srcA = g_wh + (size_t)(co_base + row)*2304 + tap*256 + ci0;
        const __half* srcB = g_xcl + ((size_t)b*IMGP + p0 + row + tap_off)*CIN + ci0;
        uint32_t dstA = sb + (uint32_t)st*STG_BYTES + (uint32_t)row*128;
        uint32_t dstB = dstA + B_OFF;
        #pragma unroll
        for (int q = 0; q < 4; ++q) {
            int c = cbase + q;
            uint32_t sw = (uint32_t)((c ^ (row & 7)) << 4);
            cp_async16(dstA + sw, srcA + c*8);
            cp_async16(dstB + sw, srcB + c*8);
        }
        cp_commit();
    };

    auto compute = [&](int bufi) {
        uint32_t ab = sb + (uint32_t)bufi*STG_BYTES;
        uint32_t bb = ab + B_OFF;
        #pragma unroll
        for (int s = 0; s < 4; ++s) {       // 4 x K16 steps
            uint32_t a[2][4];
            #pragma unroll
            for (int mt = 0; mt < 2; ++mt) {
                int m  = wm*32 + mt*16 + (lane & 15);
                int kg = s*2 + (lane >> 4);
                ldsm4(a[mt], ab + (uint32_t)m*128 + (uint32_t)((kg ^ (m&7)) << 4));
            }
            #pragma unroll
            for (int pr = 0; pr < 4; ++pr) {
                int grp = lane >> 3, r = lane & 7;
                int n = wn*64 + pr*16 + ((grp & 2) << 2) + r;
                int c = s*2 + (grp & 1);
                uint32_t bfr[4];            // (n0,k0)(n0,k8)(n0+8,k0)(n0+8,k8)
                ldsm4(bfr, bb + (uint32_t)n*128 + (uint32_t)((c ^ (n&7)) << 4));
                mma16816(acc[0][2*pr+0], a[0], &bfr[0]);
                mma16816(acc[1][2*pr+0], a[1], &bfr[0]);
                mma16816(acc[0][2*pr+1], a[0], &bfr[2]);
                mma16816(acc[1][2*pr+1], a[1], &bfr[2]);
            }
        }
    };

    // ---- 3-stage pipeline over 36 K-chunks ---------------------------------
    loadStage(0, 0);
    loadStage(1, 1);

    for (int kc = 0; kc < 36; ++kc) {
        if      (kc <= 34) cp_wait<1>();    // group kc complete
        else               cp_wait<0>();
        __syncthreads();                    // stage visible to all warps; also
                                            // protects reuse of stage kc%3
        int k2 = kc + 2;
        if (k2 < 36) loadStage(k2, k2 % NSTG);
        compute(kc % NSTG);
    }

    // ---- epilogue: scale*acc + bias, discard x>=56 / y>=56 ------------------
    #pragma unroll
    for (int mt = 0; mt < 2; ++mt) {
        #pragma unroll
        for (int half = 0; half < 2; ++half) {
            int co = co_base + wm*32 + mt*16 + (lane>>2) + half*8;
            float sc = __ldg(&scale[co]);
            float bs = __ldg(&bias[co]);
            #pragma unroll
            for (int nt = 0; nt < 8; ++nt) {
                int n = p0 + wn*64 + nt*8 + (lane&3)*2;
                int y = n / PW, x2 = n % PW;
                if (x2 < WW && y < HH) {
                    float2 v;
                    v.x = sc*acc[mt][nt][half*2+0] + bs;
                    v.y = sc*acc[mt][nt][half*2+1] + bs;
                    *(float2*)&out[(((size_t)b*COUT + co)*HH + y)*WW + x2] = v;
                }
            }
        }
    }
}

// ---------------------------------------------------------------------------
extern "C" void kernel_launch(void* const* d_in, const int* in_sizes, int n_in,
                              void* d_out, int out_size) {
    const float* x     = (const float*)d_in[0];
    const float* scale = (const float*)d_in[1];
    const float* qw    = (const float*)d_in[2];
    const float* bias  = (const float*)d_in[3];
    float* out = (float*)d_out;

    size_t z16 = ((size_t)NB*IMGP*CIN + GTAIL) / 8;
    zero_kernel<<<(unsigned)((z16 + 255)/256), 256>>>();
    dim3 tg(49, 8, NB);
    tpad_kernel<<<tg, 256>>>(x);
    wprep_kernel<<<(COUT*2304 + 255)/256, 256>>>(qw);

    cudaFuncSetAttribute(conv_kernel,
                         cudaFuncAttributeMaxDynamicSharedMemorySize, SMEM_TOTAL);
    dim3 grid(26, 2, NB);
    conv_kernel<<<grid, 256, SMEM_TOTAL>>>(scale, bias, out);
}

// round 10
// speedup vs baseline: 2.2236x; 1.0193x over previous
#include <cuda_runtime.h>
#include <cuda_fp16.h>
#include <cstdint>

#define NB   32
#define CIN  256
#define COUT 256
#define HH   56
#define WW   56
#define PW   58
#define IMGP 3368             // padded image stride (p dimension)
#define GTAIL (81*256)        // tail guard halves (tap overreach on last image)

#define TM   128
#define TN   128
#define TK   32
#define NSTG 6
#define STG_BYTES 16384       // A 8KB + B 8KB
#define B_OFF 8192
#define SMEM_TOTAL (NSTG*STG_BYTES)   // 96 KB

// channels-last padded input: g_xcl[b][p][ci], fp16
__device__ __align__(256) __half g_xcl[(size_t)NB*IMGP*CIN + GTAIL];
__device__ __align__(256) __half g_wh[COUT*2304];   // weights, k = tap*256 + ci

// ---------------------------------------------------------------------------
// Prep 0: zero ONLY the padding borders + tails (interior written by tpad).
// Per image: y=0 row (58), y=57 row (58), x=0 col (56), x=57 col (56),
// p in [3364,3368) tail (4)  => 232 positions x 256 ci = 7424 uint4.
// Plus GTAIL guard after the last image.
// ---------------------------------------------------------------------------
#define BPOS 232
#define BU4_PER_IMG (BPOS*32)                 // 7424 uint4 per image
#define BU4_TOTAL   (NB*BU4_PER_IMG + GTAIL/8)
__global__ void border_kernel() {
    int i = blockIdx.x*blockDim.x + threadIdx.x;
    if (i >= BU4_TOTAL) return;
    size_t off16;
    if (i < NB*BU4_PER_IMG) {
        int b   = i / BU4_PER_IMG;
        int idx = i % BU4_PER_IMG;
        int j   = idx >> 5;          // border position 0..231
        int c   = idx & 31;          // 8-half chunk within ci
        int p;
        if      (j < 58)  p = j;                       // y = 0 row
        else if (j < 116) p = 57*PW + (j - 58);        // y = 57 row
        else if (j < 172) p = (j - 116 + 1)*PW;        // x = 0 col, y=1..56
        else if (j < 228) p = (j - 172 + 1)*PW + 57;   // x = 57 col
        else              p = 3364 + (j - 228);        // p tail
        off16 = ((size_t)b*IMGP + p)*CIN + c*8;
    } else {
        off16 = (size_t)NB*IMGP*CIN + (size_t)(i - NB*BU4_PER_IMG)*8;
    }
    *(uint4*)(g_xcl + off16) = make_uint4(0,0,0,0);
}

// ---------------------------------------------------------------------------
// Prep 1: transpose-pad  x[b][ci][h][w] (fp32) -> g_xcl[b][(y+1)*58+(x+1)][ci]
// ---------------------------------------------------------------------------
__global__ void tpad_kernel(const float* __restrict__ x) {
    __shared__ __half st[32][68];
    const int tid = threadIdx.x;
    const int pc  = blockIdx.x * 64;
    const int cic = blockIdx.y * 32;
    const int b   = blockIdx.z;
    {
        int ci_r = tid >> 3;
        int pj   = tid & 7;
        const float* src = x + ((size_t)(b*CIN + cic + ci_r)*3136 + pc + pj*8);
        float4 v0 = *(const float4*)(src);
        float4 v1 = *(const float4*)(src + 4);
        st[ci_r][pj*8+0] = __float2half(v0.x);
        st[ci_r][pj*8+1] = __float2half(v0.y);
        st[ci_r][pj*8+2] = __float2half(v0.z);
        st[ci_r][pj*8+3] = __float2half(v0.w);
        st[ci_r][pj*8+4] = __float2half(v1.x);
        st[ci_r][pj*8+5] = __float2half(v1.y);
        st[ci_r][pj*8+6] = __float2half(v1.z);
        st[ci_r][pj*8+7] = __float2half(v1.w);
    }
    __syncthreads();
    {
        int pw = tid >> 2;
        int g  = tid & 3;
        int p  = pc + pw;
        int y  = p / 56, xx = p % 56;
        int ppad = (y+1)*PW + (xx+1);
        __half h[8];
        #pragma unroll
        for (int j = 0; j < 8; ++j) h[j] = st[g*8+j][pw];
        __half* dst = g_xcl + ((size_t)b*IMGP + ppad)*CIN + cic + g*8;
        *(uint4*)dst = *(uint4*)h;
    }
}

// ---------------------------------------------------------------------------
// Prep 2: weights -> fp16, k = tap*256 + ci
// ---------------------------------------------------------------------------
__global__ void wprep_kernel(const float* __restrict__ qw) {
    int i = blockIdx.x*blockDim.x + threadIdx.x;
    if (i < COUT*2304) {
        int co = i / 2304, rest = i % 2304;
        int ci = rest / 9, tap = rest % 9;
        g_wh[co*2304 + tap*256 + ci] = __float2half(qw[i]);
    }
}

// ---------------------------------------------------------------------------
// PTX helpers
// ---------------------------------------------------------------------------
__device__ __forceinline__ uint32_t smem_u32(const void* p) {
    uint32_t a;
    asm("{ .reg .u64 t; cvta.to.shared.u64 t, %1; cvt.u32.u64 %0, t; }"
        : "=r"(a) : "l"(p));
    return a;
}
__device__ __forceinline__ void cp_async16(uint32_t dst, const void* src) {
    asm volatile("cp.async.cg.shared.global [%0], [%1], 16;\n" :: "r"(dst), "l"(src));
}
__device__ __forceinline__ void cp_commit() {
    asm volatile("cp.async.commit_group;\n" ::: "memory");
}
template <int N>
__device__ __forceinline__ void cp_wait() {
    asm volatile("cp.async.wait_group %0;\n" :: "n"(N) : "memory");
}
__device__ __forceinline__ void ldsm4(uint32_t* r, uint32_t a) {
    asm volatile("ldmatrix.sync.aligned.m8n8.x4.shared.b16 {%0,%1,%2,%3}, [%4];"
        : "=r"(r[0]), "=r"(r[1]), "=r"(r[2]), "=r"(r[3]) : "r"(a));
}
__device__ __forceinline__ void mma16816(float* c, const uint32_t* a, const uint32_t* b) {
    asm("mma.sync.aligned.m16n8k16.row.col.f32.f16.f16.f32 "
        "{%0,%1,%2,%3}, {%4,%5,%6,%7}, {%8,%9}, {%0,%1,%2,%3};"
        : "+f"(c[0]), "+f"(c[1]), "+f"(c[2]), "+f"(c[3])
        : "r"(a[0]), "r"(a[1]), "r"(a[2]), "r"(a[3]), "r"(b[0]), "r"(b[1]));
}

// ---------------------------------------------------------------------------
// Implicit-GEMM conv:  D[co,p'] = sum_k W[co,k] * X[k,p']
// K = 2304 as 72 chunks of 32, processed in 24 windows of 3 chunks.
// 6-stage smem ring (16KB/stage), one cp_wait + one barrier PER WINDOW.
// grid = (26 p'-tiles of 128, 2 co-tiles, 32 b), 256 threads, 2 CTAs/SM
// ---------------------------------------------------------------------------
__global__ __launch_bounds__(256, 2)
void conv_kernel(const float* __restrict__ scale,
                 const float* __restrict__ bias,
                 float* __restrict__ out)
{
    extern __shared__ __align__(16) char smem[];
    const uint32_t sb = smem_u32(smem);

    const int tid  = threadIdx.x;
    const int lane = tid & 31;
    const int warp = tid >> 5;
    const int wm   = warp & 3;          // 4 m-warps (co, 32 each)
    const int wn   = warp >> 2;         // 2 n-warps (p', 64 each)
    const int b       = blockIdx.z;
    const int co_base = blockIdx.y * TM;
    const int p0      = blockIdx.x * TN;

    float acc[2][8][4];
    #pragma unroll
    for (int mt = 0; mt < 2; ++mt)
        #pragma unroll
        for (int nt = 0; nt < 8; ++nt)
            #pragma unroll
            for (int r = 0; r < 4; ++r) acc[mt][nt][r] = 0.f;

    // Load K-chunk kc (tap, 32 ci) into slot kc%6. 64B rows, 4x16B chunks,
    // swizzled chunk' = c ^ ((row>>1)&3).  (R6-proven recipe)
    auto loadStage = [&](int kc) {
        int st  = kc % NSTG;
        int tap = kc >> 3, ci0 = (kc & 7) * TK;
        int tap_off = (tap/3)*PW + (tap%3);
        int row   = tid >> 1;               // 0..127
        int cbase = (tid & 1) * 2;          // chunks 0-1 / 2-3
        const __half* srcA = g_wh + (size_t)(co_base + row)*2304 + tap*256 + ci0;
        const __half* srcB = g_xcl + ((size_t)b*IMGP + p0 + row + tap_off)*CIN + ci0;
        uint32_t dstA = sb + (uint32_t)st*STG_BYTES + (uint32_t)row*64;
        uint32_t dstB = dstA + B_OFF;
        #pragma unroll
        for (int q = 0; q < 2; ++q) {
            int c = cbase + q;
            uint32_t sw = (uint32_t)((c ^ ((row>>1)&3)) << 4);
            cp_async16(dstA + sw, srcA + c*8);
            cp_async16(dstB + sw, srcB + c*8);
        }
        cp_commit();
    };

    auto compute = [&](int kc) {
        int bufi = kc % NSTG;
        uint32_t ab = sb + (uint32_t)bufi*STG_BYTES;
        uint32_t bb = ab + B_OFF;
        #pragma unroll
        for (int s = 0; s < 2; ++s) {       // 2 x K16 steps
            uint32_t a[2][4];
            #pragma unroll
            for (int mt = 0; mt < 2; ++mt) {
                int m  = wm*32 + mt*16 + (lane & 15);
                int kg = s*2 + (lane >> 4);
                ldsm4(a[mt], ab + (uint32_t)m*64 + (uint32_t)((kg ^ ((m>>1)&3)) << 4));
            }
            #pragma unroll
            for (int pr = 0; pr < 4; ++pr) {
                int grp = lane >> 3, r = lane & 7;
                int n = wn*64 + pr*16 + ((grp & 2) << 2) + r;
                int c = s*2 + (grp & 1);
                uint32_t bfr[4];            // (n0,k0)(n0,k8)(n0+8,k0)(n0+8,k8)
                ldsm4(bfr, bb + (uint32_t)n*64 + (uint32_t)((c ^ ((n>>1)&3)) << 4));
                mma16816(acc[0][2*pr+0], a[0], &bfr[0]);
                mma16816(acc[1][2*pr+0], a[1], &bfr[0]);
                mma16816(acc[0][2*pr+1], a[0], &bfr[2]);
                mma16816(acc[1][2*pr+1], a[1], &bfr[2]);
            }
        }
    };

    // ---- 24 windows of 3 chunks (72 chunks total) ---------------------------
    loadStage(0); loadStage(1); loadStage(2);

    for (int w = 0; w < 24; ++w) {
        cp_wait<0>();                       // all in-flight groups (this window's data)
        __syncthreads();                    // visible to all warps; slots reusable
        int kc = w*3;
        if (w < 23) {                       // prefetch next window
            loadStage(kc+3); loadStage(kc+4); loadStage(kc+5);
        }
        compute(kc); compute(kc+1); compute(kc+2);
    }

    // ---- epilogue: scale*acc + bias, discard x>=56 / y>=56 ------------------
    #pragma unroll
    for (int mt = 0; mt < 2; ++mt) {
        #pragma unroll
        for (int half = 0; half < 2; ++half) {
            int co = co_base + wm*32 + mt*16 + (lane>>2) + half*8;
            float sc = __ldg(&scale[co]);
            float bs = __ldg(&bias[co]);
            #pragma unroll
            for (int nt = 0; nt < 8; ++nt) {
                int n = p0 + wn*64 + nt*8 + (lane&3)*2;
                int y = n / PW, x2 = n % PW;
                if (x2 < WW && y < HH) {
                    float2 v;
                    v.x = sc*acc[mt][nt][half*2+0] + bs;
                    v.y = sc*acc[mt][nt][half*2+1] + bs;
                    *(float2*)&out[(((size_t)b*COUT + co)*HH + y)*WW + x2] = v;
                }
            }
        }
    }
}

// ---------------------------------------------------------------------------
extern "C" void kernel_launch(void* const* d_in, const int* in_sizes, int n_in,
                              void* d_out, int out_size) {
    const float* x     = (const float*)d_in[0];
    const float* scale = (const float*)d_in[1];
    const float* qw    = (const float*)d_in[2];
    const float* bias  = (const float*)d_in[3];
    float* out = (float*)d_out;

    border_kernel<<<(BU4_TOTAL + 255)/256, 256>>>();
    dim3 tg(49, 8, NB);
    tpad_kernel<<<tg, 256>>>(x);
    wprep_kernel<<<(COUT*2304 + 255)/256, 256>>>(qw);

    cudaFuncSetAttribute(conv_kernel,
                         cudaFuncAttributeMaxDynamicSharedMemorySize, SMEM_TOTAL);
    dim3 grid(26, 2, NB);
    conv_kernel<<<grid, 256, SMEM_TOTAL>>>(scale, bias, out);
}

// round 11
// speedup vs baseline: 2.5530x; 1.1482x over previous
#include <cuda_runtime.h>
#include <cuda_fp16.h>
#include <cstdint>

#define NB   32
#define CIN  256
#define COUT 256
#define HH   56
#define WW   56
#define PW   58
#define IMGP 3368             // padded image stride (p dimension)
#define GTAIL (81*256)        // tail guard halves (tap/tile overreach on last image)

#define TM   128
#define TN   96
#define TK   32
#define NSTG 6
#define STG_BYTES 14336       // A 8KB + B 6KB
#define B_OFF 8192
#define SMEM_TOTAL (NSTG*STG_BYTES)   // 84 KB
#define NTHR 384

// channels-last padded input: g_xcl[b][p][ci], fp16
__device__ __align__(256) __half g_xcl[(size_t)NB*IMGP*CIN + GTAIL];
__device__ __align__(256) __half g_wh[COUT*2304];   // weights, k = tap*256 + ci

// ---------------------------------------------------------------------------
// Prep 0: zero ONLY padding borders + tails (interior written by tpad).
// ---------------------------------------------------------------------------
#define BPOS 232
#define BU4_PER_IMG (BPOS*32)                 // 7424 uint4 per image
#define BU4_TOTAL   (NB*BU4_PER_IMG + GTAIL/8)
__global__ void border_kernel() {
    int i = blockIdx.x*blockDim.x + threadIdx.x;
    if (i >= BU4_TOTAL) return;
    size_t off16;
    if (i < NB*BU4_PER_IMG) {
        int b   = i / BU4_PER_IMG;
        int idx = i % BU4_PER_IMG;
        int j   = idx >> 5;
        int c   = idx & 31;
        int p;
        if      (j < 58)  p = j;                       // y = 0 row
        else if (j < 116) p = 57*PW + (j - 58);        // y = 57 row
        else if (j < 172) p = (j - 116 + 1)*PW;        // x = 0 col
        else if (j < 228) p = (j - 172 + 1)*PW + 57;   // x = 57 col
        else              p = 3364 + (j - 228);        // p tail
        off16 = ((size_t)b*IMGP + p)*CIN + c*8;
    } else {
        off16 = (size_t)NB*IMGP*CIN + (size_t)(i - NB*BU4_PER_IMG)*8;
    }
    *(uint4*)(g_xcl + off16) = make_uint4(0,0,0,0);
}

// ---------------------------------------------------------------------------
// Prep 1: transpose-pad  x[b][ci][h][w] (fp32) -> g_xcl[b][(y+1)*58+(x+1)][ci]
// ---------------------------------------------------------------------------
__global__ void tpad_kernel(const float* __restrict__ x) {
    __shared__ __half st[32][68];
    const int tid = threadIdx.x;
    const int pc  = blockIdx.x * 64;
    const int cic = blockIdx.y * 32;
    const int b   = blockIdx.z;
    {
        int ci_r = tid >> 3;
        int pj   = tid & 7;
        const float* src = x + ((size_t)(b*CIN + cic + ci_r)*3136 + pc + pj*8);
        float4 v0 = *(const float4*)(src);
        float4 v1 = *(const float4*)(src + 4);
        st[ci_r][pj*8+0] = __float2half(v0.x);
        st[ci_r][pj*8+1] = __float2half(v0.y);
        st[ci_r][pj*8+2] = __float2half(v0.z);
        st[ci_r][pj*8+3] = __float2half(v0.w);
        st[ci_r][pj*8+4] = __float2half(v1.x);
        st[ci_r][pj*8+5] = __float2half(v1.y);
        st[ci_r][pj*8+6] = __float2half(v1.z);
        st[ci_r][pj*8+7] = __float2half(v1.w);
    }
    __syncthreads();
    {
        int pw = tid >> 2;
        int g  = tid & 3;
        int p  = pc + pw;
        int y  = p / 56, xx = p % 56;
        int ppad = (y+1)*PW + (xx+1);
        __half h[8];
        #pragma unroll
        for (int j = 0; j < 8; ++j) h[j] = st[g*8+j][pw];
        __half* dst = g_xcl + ((size_t)b*IMGP + ppad)*CIN + cic + g*8;
        *(uint4*)dst = *(uint4*)h;
    }
}

// ---------------------------------------------------------------------------
// Prep 2: weights -> fp16, k = tap*256 + ci
// ---------------------------------------------------------------------------
__global__ void wprep_kernel(const float* __restrict__ qw) {
    int i = blockIdx.x*blockDim.x + threadIdx.x;
    if (i < COUT*2304) {
        int co = i / 2304, rest = i % 2304;
        int ci = rest / 9, tap = rest % 9;
        g_wh[co*2304 + tap*256 + ci] = __float2half(qw[i]);
    }
}

// ---------------------------------------------------------------------------
// PTX helpers
// ---------------------------------------------------------------------------
__device__ __forceinline__ uint32_t smem_u32(const void* p) {
    uint32_t a;
    asm("{ .reg .u64 t; cvta.to.shared.u64 t, %1; cvt.u32.u64 %0, t; }"
        : "=r"(a) : "l"(p));
    return a;
}
__device__ __forceinline__ void cp_async16(uint32_t dst, const void* src) {
    asm volatile("cp.async.cg.shared.global [%0], [%1], 16;\n" :: "r"(dst), "l"(src));
}
__device__ __forceinline__ void cp_commit() {
    asm volatile("cp.async.commit_group;\n" ::: "memory");
}
template <int N>
__device__ __forceinline__ void cp_wait() {
    asm volatile("cp.async.wait_group %0;\n" :: "n"(N) : "memory");
}
__device__ __forceinline__ void ldsm4(uint32_t* r, uint32_t a) {
    asm volatile("ldmatrix.sync.aligned.m8n8.x4.shared.b16 {%0,%1,%2,%3}, [%4];"
        : "=r"(r[0]), "=r"(r[1]), "=r"(r[2]), "=r"(r[3]) : "r"(a));
}
__device__ __forceinline__ void mma16816(float* c, const uint32_t* a, const uint32_t* b) {
    asm("mma.sync.aligned.m16n8k16.row.col.f32.f16.f16.f32 "
        "{%0,%1,%2,%3}, {%4,%5,%6,%7}, {%8,%9}, {%0,%1,%2,%3};"
        : "+f"(c[0]), "+f"(c[1]), "+f"(c[2]), "+f"(c[3])
        : "r"(a[0]), "r"(a[1]), "r"(a[2]), "r"(a[3]), "r"(b[0]), "r"(b[1]));
}

// ---------------------------------------------------------------------------
// Implicit-GEMM conv:  D[co,p'] = sum_k W[co,k] * X[k,p']
// K = 2304 as 72 chunks of 32, windows of 3 chunks, 6-stage smem ring.
// 384 threads = 12 warps (wm4 x wn3), warp tile 32co x 32n (32 acc regs).
// grid = (34 p'-tiles of 96, 2 co-tiles, 32 b), 2 CTAs/SM -> 24 warps/SM.
// ---------------------------------------------------------------------------
__global__ __launch_bounds__(NTHR, 2)
void conv_kernel(const float* __restrict__ scale,
                 const float* __restrict__ bias,
                 float* __restrict__ out)
{
    extern __shared__ __align__(16) char smem[];
    const uint32_t sb = smem_u32(smem);

    const int tid  = threadIdx.x;
    const int lane = tid & 31;
    const int warp = tid >> 5;
    const int wm   = warp & 3;          // 4 m-warps (co, 32 each)
    const int wn   = warp >> 2;         // 3 n-warps (p', 32 each)
    const int b       = blockIdx.z;
    const int co_base = blockIdx.y * TM;
    const int p0      = blockIdx.x * TN;

    float acc[2][4][4];
    #pragma unroll
    for (int mt = 0; mt < 2; ++mt)
        #pragma unroll
        for (int nt = 0; nt < 4; ++nt)
            #pragma unroll
            for (int r = 0; r < 4; ++r) acc[mt][nt][r] = 0.f;

    // Load K-chunk kc into slot kc%6. A: 128 rows x 64B (512 x 16B chunks),
    // B: 96 rows x 64B (384 chunks). 896 chunks over 384 threads (<=3 each).
    // Swizzle chunk' = c ^ ((row>>1)&3).
    auto loadStage = [&](int kc) {
        int st  = kc % NSTG;
        int tap = kc >> 3, ci0 = (kc & 7) * TK;
        int tap_off = (tap/3)*PW + (tap%3);
        uint32_t base = sb + (uint32_t)st*STG_BYTES;
        #pragma unroll
        for (int t = 0; t < 3; ++t) {
            int idx = tid + t*NTHR;
            if (t < 2 || idx < 896) {
                if (idx < 512) {
                    int row = idx >> 2, c = idx & 3;
                    const __half* src = g_wh + (size_t)(co_base + row)*2304
                                             + tap*256 + ci0 + c*8;
                    uint32_t sw = (uint32_t)((c ^ ((row>>1)&3)) << 4);
                    cp_async16(base + (uint32_t)row*64 + sw, src);
                } else {
                    int j = idx - 512;
                    int row = j >> 2, c = j & 3;
                    const __half* src = g_xcl + ((size_t)b*IMGP + p0 + row + tap_off)*CIN
                                              + ci0 + c*8;
                    uint32_t sw = (uint32_t)((c ^ ((row>>1)&3)) << 4);
                    cp_async16(base + B_OFF + (uint32_t)row*64 + sw, src);
                }
            }
        }
        cp_commit();
    };

    auto compute = [&](int kc) {
        int bufi = kc % NSTG;
        uint32_t ab = sb + (uint32_t)bufi*STG_BYTES;
        uint32_t bb = ab + B_OFF;
        #pragma unroll
        for (int s = 0; s < 2; ++s) {       // 2 x K16 steps
            uint32_t a[2][4];
            #pragma unroll
            for (int mt = 0; mt < 2; ++mt) {
                int m  = wm*32 + mt*16 + (lane & 15);
                int kg = s*2 + (lane >> 4);
                ldsm4(a[mt], ab + (uint32_t)m*64 + (uint32_t)((kg ^ ((m>>1)&3)) << 4));
            }
            #pragma unroll
            for (int pr = 0; pr < 2; ++pr) {
                int grp = lane >> 3, r = lane & 7;
                int n = wn*32 + pr*16 + ((grp & 2) << 2) + r;
                int c = s*2 + (grp & 1);
                uint32_t bfr[4];            // (n0,k0)(n0,k8)(n0+8,k0)(n0+8,k8)
                ldsm4(bfr, bb + (uint32_t)n*64 + (uint32_t)((c ^ ((n>>1)&3)) << 4));
                mma16816(acc[0][2*pr+0], a[0], &bfr[0]);
                mma16816(acc[1][2*pr+0], a[1], &bfr[0]);
                mma16816(acc[0][2*pr+1], a[0], &bfr[2]);
                mma16816(acc[1][2*pr+1], a[1], &bfr[2]);
            }
        }
    };

    // ---- 24 windows of 3 chunks (72 chunks total) ---------------------------
    loadStage(0); loadStage(1); loadStage(2);

    for (int w = 0; w < 24; ++w) {
        cp_wait<0>();
        __syncthreads();
        int kc = w*3;
        if (w < 23) {
            loadStage(kc+3); loadStage(kc+4); loadStage(kc+5);
        }
        compute(kc); compute(kc+1); compute(kc+2);
    }

    // ---- epilogue: scale*acc + bias, discard x>=56 / y>=56 / p'>=3248 -------
    #pragma unroll
    for (int mt = 0; mt < 2; ++mt) {
        #pragma unroll
        for (int half = 0; half < 2; ++half) {
            int co = co_base + wm*32 + mt*16 + (lane>>2) + half*8;
            float sc = __ldg(&scale[co]);
            float bs = __ldg(&bias[co]);
            #pragma unroll
            for (int nt = 0; nt < 4; ++nt) {
                int n = p0 + wn*32 + nt*8 + (lane&3)*2;
                int y = n / PW, x2 = n % PW;
                if (x2 < WW && y < HH) {
                    float2 v;
                    v.x = sc*acc[mt][nt][half*2+0] + bs;
                    v.y = sc*acc[mt][nt][half*2+1] + bs;
                    *(float2*)&out[(((size_t)b*COUT + co)*HH + y)*WW + x2] = v;
                }
            }
        }
    }
}

// ---------------------------------------------------------------------------
extern "C" void kernel_launch(void* const* d_in, const int* in_sizes, int n_in,
                              void* d_out, int out_size) {
    const float* x     = (const float*)d_in[0];
    const float* scale = (const float*)d_in[1];
    const float* qw    = (const float*)d_in[2];
    const float* bias  = (const float*)d_in[3];
    float* out = (float*)d_out;

    border_kernel<<<(BU4_TOTAL + 255)/256, 256>>>();
    dim3 tg(49, 8, NB);
    tpad_kernel<<<tg, 256>>>(x);
    wprep_kernel<<<(COUT*2304 + 255)/256, 256>>>(qw);

    cudaFuncSetAttribute(conv_kernel,
                         cudaFuncAttributeMaxDynamicSharedMemorySize, SMEM_TOTAL);
    dim3 grid(34, 2, NB);   // 34 p'-tiles of 96 (58*56=3248), 2 co-tiles, 32 b
    conv_kernel<<<grid, NTHR, SMEM_TOTAL>>>(scale, bias, out);
}